// round 5
// baseline (speedup 1.0000x reference)
#include <cuda_runtime.h>
#include <cuda_bf16.h>
#include <cstdint>

// Problem dims
#define NXR 8192
#define NYR 8192
#define DK  512

// Tile config: CTA 128x128, 8 warps each 32x64, K-step 32, 4 stages, 2 CTAs/SM
#define TM 128
#define TN 128
#define TK 32
#define KSTEPS (DK / TK)          // 16
#define STAGES 4

// SMEM: rows padded to 40 b16 (80B) for conflict-free ldmatrix.
#define ASTRIDE_B16 40
#define A_TILE_BYTES (TM * ASTRIDE_B16 * 2)         // 10240
#define B_TILE_BYTES (TN * ASTRIDE_B16 * 2)         // 10240
#define STAGE_BYTES  (A_TILE_BYTES + B_TILE_BYTES)  // 20480
#define SMEM_TOTAL   (STAGES * STAGE_BYTES)         // 81920

// bf16 scratch + row norms (device globals: no allocation allowed)
__device__ __nv_bfloat16 g_Xb[(size_t)NXR * DK];
__device__ __nv_bfloat16 g_Yb[(size_t)NYR * DK];
__device__ float g_x2[NXR];
__device__ float g_y2[NYR];

// ---------------- PTX helpers ----------------
__device__ __forceinline__ uint32_t smem_u32(const void* p) {
    uint32_t a;
    asm("{ .reg .u64 t; cvta.to.shared.u64 t, %1; cvt.u32.u64 %0, t; }" : "=r"(a) : "l"(p));
    return a;
}

#define CP_ASYNC16(saddr, gptr) \
    asm volatile("cp.async.cg.shared.global [%0], [%1], 16;" \
                 :: "r"(saddr), "l"(gptr) : "memory")

#define CP_COMMIT() asm volatile("cp.async.commit_group;" ::: "memory")
#define CP_WAIT(n)  asm volatile("cp.async.wait_group %0;" :: "n"(n) : "memory")

#define LDSM_X4(r, addr) \
    asm volatile("ldmatrix.sync.aligned.m8n8.x4.shared.b16 {%0,%1,%2,%3}, [%4];" \
                 : "=r"((r)[0]), "=r"((r)[1]), "=r"((r)[2]), "=r"((r)[3]) : "r"(addr))

#define MMA16816(d, a, b0, b1) \
    asm volatile("mma.sync.aligned.m16n8k16.row.col.f32.bf16.bf16.f32 " \
                 "{%0,%1,%2,%3}, {%4,%5,%6,%7}, {%8,%9}, {%0,%1,%2,%3};" \
                 : "+f"((d)[0]), "+f"((d)[1]), "+f"((d)[2]), "+f"((d)[3]) \
                 : "r"((a)[0]), "r"((a)[1]), "r"((a)[2]), "r"((a)[3]), \
                   "r"(b0), "r"(b1))

// ---------------- Prepass: f32 -> bf16 + row squared norms ----------------
__global__ void __launch_bounds__(128) rbf_prep_kernel(
    const float* __restrict__ x, const float* __restrict__ y) {
    __shared__ float red[4];
    int b = blockIdx.x;
    int t = threadIdx.x;
    const float* src;
    __nv_bfloat16* dst;
    float* nrm;
    int row;
    if (b < NXR) { row = b;       src = x + (size_t)row * DK; dst = g_Xb + (size_t)row * DK; nrm = g_x2; }
    else         { row = b - NXR; src = y + (size_t)row * DK; dst = g_Yb + (size_t)row * DK; nrm = g_y2; }

    float4 v = reinterpret_cast<const float4*>(src)[t];          // 128 threads x 4 = 512
    float s = v.x * v.x + v.y * v.y + v.z * v.z + v.w * v.w;
    __nv_bfloat162 h0 = __floats2bfloat162_rn(v.x, v.y);
    __nv_bfloat162 h1 = __floats2bfloat162_rn(v.z, v.w);
    reinterpret_cast<__nv_bfloat162*>(dst)[t * 2 + 0] = h0;
    reinterpret_cast<__nv_bfloat162*>(dst)[t * 2 + 1] = h1;

    #pragma unroll
    for (int o = 16; o; o >>= 1) s += __shfl_xor_sync(0xffffffffu, s, o);
    if ((t & 31) == 0) red[t >> 5] = s;
    __syncthreads();
    if (t == 0) nrm[row] = red[0] + red[1] + red[2] + red[3];
}

// ---------------- Main kernel: pipelined mma.sync GEMM + RBF epilogue ----------------
__global__ void __launch_bounds__(256, 2) rbf_gemm_kernel(
    float* __restrict__ out, const float* __restrict__ gamma_p) {
    extern __shared__ char smem[];
    const uint32_t sb = smem_u32(smem);
    const int tid = threadIdx.x;
    const int wid = tid >> 5;
    const int lid = tid & 31;
    const int wm = wid & 3;            // warp row: 32-row slab (4)
    const int wn = wid >> 2;           // warp col: 64-col slab (2)
    const int mbase = blockIdx.y * TM;
    const int nbase = blockIdx.x * TN;

    // ---- per-thread cp.async assignment: 2 chunks A + 2 chunks B per stage ----
    const int arow0 = tid >> 2,            aseg0 = tid & 3;
    const int arow1 = (tid + 256) >> 2,    aseg1 = (tid + 256) & 3;
    const __nv_bfloat16* aptr0 = g_Xb + (size_t)(mbase + arow0) * DK + aseg0 * 8;
    const __nv_bfloat16* aptr1 = g_Xb + (size_t)(mbase + arow1) * DK + aseg1 * 8;
    const __nv_bfloat16* bptr0 = g_Yb + (size_t)(nbase + arow0) * DK + aseg0 * 8;
    const __nv_bfloat16* bptr1 = g_Yb + (size_t)(nbase + arow1) * DK + aseg1 * 8;
    const uint32_t soA0 = (uint32_t)(arow0 * (ASTRIDE_B16 * 2) + aseg0 * 16);
    const uint32_t soA1 = (uint32_t)(arow1 * (ASTRIDE_B16 * 2) + aseg1 * 16);

    int ldk = 0;  // next k-step to load
    #pragma unroll
    for (int s = 0; s < STAGES - 1; s++) {
        const uint32_t st = sb + s * STAGE_BYTES;
        CP_ASYNC16(st + soA0, aptr0 + ldk * TK);
        CP_ASYNC16(st + soA1, aptr1 + ldk * TK);
        CP_ASYNC16(st + A_TILE_BYTES + soA0, bptr0 + ldk * TK);
        CP_ASYNC16(st + A_TILE_BYTES + soA1, bptr1 + ldk * TK);
        CP_COMMIT();
        ldk++;
    }

    // acc[tm 0..1][nn 0..7][4] : warp 32x64 tile
    float acc[2][8][4];
    #pragma unroll
    for (int i = 0; i < 2; i++)
        #pragma unroll
        for (int j = 0; j < 8; j++)
            #pragma unroll
            for (int q = 0; q < 4; q++) acc[i][j][q] = 0.0f;

    const int lrow = lid & 15;
    const int lhalf = lid >> 4;
    const uint32_t aoff = (uint32_t)((wm * 32 + lrow) * 80 + lhalf * 16);
    const uint32_t boff = (uint32_t)(A_TILE_BYTES + (wn * 64 + lrow) * 80 + lhalf * 16);

    // Prologue: stage 0 ready, prefetch b_cur = B(0, kk=0)
    CP_WAIT(STAGES - 2);
    __syncthreads();
    uint32_t bcur[4][4], bnxt[4][4], afr[2][4];
    #pragma unroll
    for (int p = 0; p < 4; p++)
        LDSM_X4(bcur[p], sb + boff + p * (16 * 80));

    for (int k = 0; k < KSTEPS; k++) {
        const uint32_t st = sb + (k & (STAGES - 1)) * STAGE_BYTES;

        // ---- half kk=0: prefetch B(k,1) and A(k,0); MMA on b_cur ----
        #pragma unroll
        for (int p = 0; p < 4; p++)
            LDSM_X4(bnxt[p], st + boff + 32 + p * (16 * 80));
        #pragma unroll
        for (int tm = 0; tm < 2; tm++)
            LDSM_X4(afr[tm], st + aoff + tm * (16 * 80));

        #pragma unroll
        for (int tm = 0; tm < 2; tm++)
            #pragma unroll
            for (int p = 0; p < 4; p++) {
                MMA16816(acc[tm][2 * p + 0], afr[tm], bcur[p][0], bcur[p][2]);
                MMA16816(acc[tm][2 * p + 1], afr[tm], bcur[p][1], bcur[p][3]);
            }

        // ---- half kk=1: A(k,1) read BEFORE the barrier (stage k still safe) ----
        #pragma unroll
        for (int tm = 0; tm < 2; tm++)
            LDSM_X4(afr[tm], st + aoff + 32 + tm * (16 * 80));

        if (ldk < KSTEPS) {
            const uint32_t ls = sb + (ldk & (STAGES - 1)) * STAGE_BYTES;
            CP_ASYNC16(ls + soA0, aptr0 + ldk * TK);
            CP_ASYNC16(ls + soA1, aptr1 + ldk * TK);
            CP_ASYNC16(ls + A_TILE_BYTES + soA0, bptr0 + ldk * TK);
            CP_ASYNC16(ls + A_TILE_BYTES + soA1, bptr1 + ldk * TK);
            ldk++;
        }
        CP_COMMIT();
        CP_WAIT(STAGES - 2);
        __syncthreads();

        // Prefetch b_cur for (k+1, kk=0) — stage k+1 just guaranteed ready.
        if (k + 1 < KSTEPS) {
            const uint32_t sn = sb + ((k + 1) & (STAGES - 1)) * STAGE_BYTES;
            #pragma unroll
            for (int p = 0; p < 4; p++)
                LDSM_X4(bcur[p], sn + boff + p * (16 * 80));
        }

        #pragma unroll
        for (int tm = 0; tm < 2; tm++)
            #pragma unroll
            for (int p = 0; p < 4; p++) {
                MMA16816(acc[tm][2 * p + 0], afr[tm], bnxt[p][0], bnxt[p][2]);
                MMA16816(acc[tm][2 * p + 1], afr[tm], bnxt[p][1], bnxt[p][3]);
            }
    }

    // ---------------- Epilogue ----------------
    const float gam = __ldg(gamma_p);
    #pragma unroll
    for (int tm = 0; tm < 2; tm++) {
        const int m0 = mbase + wm * 32 + tm * 16 + (lid >> 2);
        const float x2a = g_x2[m0];
        const float x2b = g_x2[m0 + 8];
        #pragma unroll
        for (int nn = 0; nn < 8; nn++) {
            const int n0 = nbase + wn * 64 + nn * 8 + (lid & 3) * 2;
            const float y2a = g_y2[n0];
            const float y2b = g_y2[n0 + 1];
            const float* c = acc[tm][nn];
            float2 v0, v1;
            v0.x = __expf(-gam * fmaxf(x2a + y2a - 2.0f * c[0], 0.0f));
            v0.y = __expf(-gam * fmaxf(x2a + y2b - 2.0f * c[1], 0.0f));
            v1.x = __expf(-gam * fmaxf(x2b + y2a - 2.0f * c[2], 0.0f));
            v1.y = __expf(-gam * fmaxf(x2b + y2b - 2.0f * c[3], 0.0f));
            *reinterpret_cast<float2*>(out + (size_t)m0 * NYR + n0) = v0;
            *reinterpret_cast<float2*>(out + (size_t)(m0 + 8) * NYR + n0) = v1;
        }
    }
}

extern "C" void kernel_launch(void* const* d_in, const int* in_sizes, int n_in,
                              void* d_out, int out_size) {
    const float* x = (const float*)d_in[0];
    const float* y = (const float*)d_in[1];
    const float* gamma = (const float*)d_in[2];
    float* out = (float*)d_out;

    rbf_prep_kernel<<<NXR + NYR, 128>>>(x, y);

    cudaFuncSetAttribute(rbf_gemm_kernel,
                         cudaFuncAttributeMaxDynamicSharedMemorySize, SMEM_TOTAL);
    dim3 grid(NYR / TN, NXR / TM);
    rbf_gemm_kernel<<<grid, 256, SMEM_TOTAL>>>(out, gamma);
}

// round 7
// speedup vs baseline: 1.0572x; 1.0572x over previous
#include <cuda_runtime.h>
#include <cuda_bf16.h>
#include <cstdint>

// Problem dims
#define NXR 8192
#define NYR 8192
#define DK  512

// Tile config: CTA 128x128, 8 warps each 32x64, K-step 64, 3 stages, 2 CTAs/SM
#define TM 128
#define TN 128
#define TK 64
#define KSTEPS (DK / TK)          // 8
#define STAGES 3

// SMEM: rows padded to 72 b16 (144B) for conflict-free ldmatrix
// (16B-unit starts per 8-row group: 16*r mod 128 -> 0,16,...,112 all distinct).
#define ASTRIDE_B16 72
#define ROW_BYTES    (ASTRIDE_B16 * 2)               // 144
#define A_TILE_BYTES (TM * ROW_BYTES)                // 18432
#define B_TILE_BYTES (TN * ROW_BYTES)                // 18432
#define STAGE_BYTES  (A_TILE_BYTES + B_TILE_BYTES)   // 36864
#define SMEM_TOTAL   (STAGES * STAGE_BYTES)          // 110592

// bf16 scratch + row norms (device globals: no allocation allowed)
__device__ __nv_bfloat16 g_Xb[(size_t)NXR * DK];
__device__ __nv_bfloat16 g_Yb[(size_t)NYR * DK];
__device__ float g_x2[NXR];
__device__ float g_y2[NYR];

// ---------------- PTX helpers ----------------
__device__ __forceinline__ uint32_t smem_u32(const void* p) {
    uint32_t a;
    asm("{ .reg .u64 t; cvta.to.shared.u64 t, %1; cvt.u32.u64 %0, t; }" : "=r"(a) : "l"(p));
    return a;
}

#define CP_ASYNC16(saddr, gptr) \
    asm volatile("cp.async.cg.shared.global [%0], [%1], 16;" \
                 :: "r"(saddr), "l"(gptr) : "memory")

#define CP_COMMIT() asm volatile("cp.async.commit_group;" ::: "memory")
#define CP_WAIT(n)  asm volatile("cp.async.wait_group %0;" :: "n"(n) : "memory")

#define LDSM_X4(r, addr) \
    asm volatile("ldmatrix.sync.aligned.m8n8.x4.shared.b16 {%0,%1,%2,%3}, [%4];" \
                 : "=r"((r)[0]), "=r"((r)[1]), "=r"((r)[2]), "=r"((r)[3]) : "r"(addr))

#define MMA16816(d, a, b0, b1) \
    asm volatile("mma.sync.aligned.m16n8k16.row.col.f32.bf16.bf16.f32 " \
                 "{%0,%1,%2,%3}, {%4,%5,%6,%7}, {%8,%9}, {%0,%1,%2,%3};" \
                 : "+f"((d)[0]), "+f"((d)[1]), "+f"((d)[2]), "+f"((d)[3]) \
                 : "r"((a)[0]), "r"((a)[1]), "r"((a)[2]), "r"((a)[3]), \
                   "r"(b0), "r"(b1))

// ---------------- Prepass: f32 -> bf16 + row squared norms ----------------
__global__ void __launch_bounds__(128) rbf_prep_kernel(
    const float* __restrict__ x, const float* __restrict__ y) {
    __shared__ float red[4];
    int b = blockIdx.x;
    int t = threadIdx.x;
    const float* src;
    __nv_bfloat16* dst;
    float* nrm;
    int row;
    if (b < NXR) { row = b;       src = x + (size_t)row * DK; dst = g_Xb + (size_t)row * DK; nrm = g_x2; }
    else         { row = b - NXR; src = y + (size_t)row * DK; dst = g_Yb + (size_t)row * DK; nrm = g_y2; }

    float4 v = reinterpret_cast<const float4*>(src)[t];          // 128 threads x 4 = 512
    float s = v.x * v.x + v.y * v.y + v.z * v.z + v.w * v.w;
    __nv_bfloat162 h0 = __floats2bfloat162_rn(v.x, v.y);
    __nv_bfloat162 h1 = __floats2bfloat162_rn(v.z, v.w);
    reinterpret_cast<__nv_bfloat162*>(dst)[t * 2 + 0] = h0;
    reinterpret_cast<__nv_bfloat162*>(dst)[t * 2 + 1] = h1;

    #pragma unroll
    for (int o = 16; o; o >>= 1) s += __shfl_xor_sync(0xffffffffu, s, o);
    if ((t & 31) == 0) red[t >> 5] = s;
    __syncthreads();
    if (t == 0) nrm[row] = red[0] + red[1] + red[2] + red[3];
}

// ---------------- Main kernel: pipelined mma.sync GEMM + RBF epilogue ----------------
__global__ void __launch_bounds__(256, 2) rbf_gemm_kernel(
    float* __restrict__ out, const float* __restrict__ gamma_p) {
    extern __shared__ char smem[];
    const uint32_t sb = smem_u32(smem);
    const int tid = threadIdx.x;
    const int wid = tid >> 5;
    const int lid = tid & 31;
    const int wm = wid & 3;            // warp row: 32-row slab (4)
    const int wn = wid >> 2;           // warp col: 64-col slab (2)
    const int mbase = blockIdx.y * TM;
    const int nbase = blockIdx.x * TN;

    // ---- cp.async assignment: A/B each 128 rows x 8 segs(16B) = 1024 chunks,
    //      4 per thread. idx = tid + h*256, row = idx>>3, seg = idx&7.
    const int lr0 = tid >> 3,           ls0 = tid & 7;
    const int lr1 = (tid + 256) >> 3,   ls1 = (tid + 256) & 7;
    const int lr2 = (tid + 512) >> 3,   ls2 = (tid + 512) & 7;
    const int lr3 = (tid + 768) >> 3,   ls3 = (tid + 768) & 7;
    const __nv_bfloat16* ap0 = g_Xb + (size_t)(mbase + lr0) * DK + ls0 * 8;
    const __nv_bfloat16* ap1 = g_Xb + (size_t)(mbase + lr1) * DK + ls1 * 8;
    const __nv_bfloat16* ap2 = g_Xb + (size_t)(mbase + lr2) * DK + ls2 * 8;
    const __nv_bfloat16* ap3 = g_Xb + (size_t)(mbase + lr3) * DK + ls3 * 8;
    const __nv_bfloat16* bp0 = g_Yb + (size_t)(nbase + lr0) * DK + ls0 * 8;
    const __nv_bfloat16* bp1 = g_Yb + (size_t)(nbase + lr1) * DK + ls1 * 8;
    const __nv_bfloat16* bp2 = g_Yb + (size_t)(nbase + lr2) * DK + ls2 * 8;
    const __nv_bfloat16* bp3 = g_Yb + (size_t)(nbase + lr3) * DK + ls3 * 8;
    const uint32_t so0 = (uint32_t)(lr0 * ROW_BYTES + ls0 * 16);
    const uint32_t so1 = (uint32_t)(lr1 * ROW_BYTES + ls1 * 16);
    const uint32_t so2 = (uint32_t)(lr2 * ROW_BYTES + ls2 * 16);
    const uint32_t so3 = (uint32_t)(lr3 * ROW_BYTES + ls3 * 16);

    int ldk = 0;  // next k-step (of TK=64) to load
    #pragma unroll
    for (int s = 0; s < STAGES - 1; s++) {
        const uint32_t st = sb + s * STAGE_BYTES;
        CP_ASYNC16(st + so0, ap0 + ldk * TK);
        CP_ASYNC16(st + so1, ap1 + ldk * TK);
        CP_ASYNC16(st + so2, ap2 + ldk * TK);
        CP_ASYNC16(st + so3, ap3 + ldk * TK);
        CP_ASYNC16(st + A_TILE_BYTES + so0, bp0 + ldk * TK);
        CP_ASYNC16(st + A_TILE_BYTES + so1, bp1 + ldk * TK);
        CP_ASYNC16(st + A_TILE_BYTES + so2, bp2 + ldk * TK);
        CP_ASYNC16(st + A_TILE_BYTES + so3, bp3 + ldk * TK);
        CP_COMMIT();
        ldk++;
    }

    // acc[tm 0..1][nn 0..7][4] : warp 32x64 tile
    float acc[2][8][4];
    #pragma unroll
    for (int i = 0; i < 2; i++)
        #pragma unroll
        for (int j = 0; j < 8; j++)
            #pragma unroll
            for (int q = 0; q < 4; q++) acc[i][j][q] = 0.0f;

    const int lrow = lid & 15;
    const int lhalf = lid >> 4;
    const uint32_t aoff = (uint32_t)((wm * 32 + lrow) * ROW_BYTES + lhalf * 16);
    const uint32_t boff = (uint32_t)(A_TILE_BYTES + (wn * 64 + lrow) * ROW_BYTES + lhalf * 16);

    // Prologue: stage 0 ready, prefetch b_cur = B(0, kk=0)
    CP_WAIT(STAGES - 2);
    __syncthreads();
    uint32_t bcur[4][4], bnxt[4][4], afr[2][4];
    #pragma unroll
    for (int p = 0; p < 4; p++)
        LDSM_X4(bcur[p], sb + boff + p * (16 * ROW_BYTES));

    for (int k = 0; k < KSTEPS; k++) {
        const uint32_t st = sb + (k % STAGES) * STAGE_BYTES;

        // ---- kk = 0..2: prefetch next-half B (at (kk+1)*32) and this-half A
        //      (at kk*32), MMA on bcur ----
        #pragma unroll
        for (int kk = 0; kk < 3; kk++) {
            #pragma unroll
            for (int p = 0; p < 4; p++)
                LDSM_X4(bnxt[p], st + boff + (kk + 1) * 32 + p * (16 * ROW_BYTES));
            #pragma unroll
            for (int tm = 0; tm < 2; tm++)
                LDSM_X4(afr[tm], st + aoff + kk * 32 + tm * (16 * ROW_BYTES));

            #pragma unroll
            for (int tm = 0; tm < 2; tm++)
                #pragma unroll
                for (int p = 0; p < 4; p++) {
                    MMA16816(acc[tm][2 * p + 0], afr[tm], bcur[p][0], bcur[p][2]);
                    MMA16816(acc[tm][2 * p + 1], afr[tm], bcur[p][1], bcur[p][3]);
                }
            #pragma unroll
            for (int p = 0; p < 4; p++)
                #pragma unroll
                for (int q = 0; q < 4; q++) bcur[p][q] = bnxt[p][q];
        }

        // ---- kk = 3: A read BEFORE the barrier (stage k still valid) ----
        #pragma unroll
        for (int tm = 0; tm < 2; tm++)
            LDSM_X4(afr[tm], st + aoff + 3 * 32 + tm * (16 * ROW_BYTES));

        if (ldk < KSTEPS) {
            const uint32_t ls = sb + (ldk % STAGES) * STAGE_BYTES;
            CP_ASYNC16(ls + so0, ap0 + ldk * TK);
            CP_ASYNC16(ls + so1, ap1 + ldk * TK);
            CP_ASYNC16(ls + so2, ap2 + ldk * TK);
            CP_ASYNC16(ls + so3, ap3 + ldk * TK);
            CP_ASYNC16(ls + A_TILE_BYTES + so0, bp0 + ldk * TK);
            CP_ASYNC16(ls + A_TILE_BYTES + so1, bp1 + ldk * TK);
            CP_ASYNC16(ls + A_TILE_BYTES + so2, bp2 + ldk * TK);
            CP_ASYNC16(ls + A_TILE_BYTES + so3, bp3 + ldk * TK);
            ldk++;
        }
        CP_COMMIT();
        CP_WAIT(STAGES - 2);
        __syncthreads();

        // Prefetch bcur for (k+1, kk=0) — stage k+1 just guaranteed ready.
        if (k + 1 < KSTEPS) {
            const uint32_t sn = sb + ((k + 1) % STAGES) * STAGE_BYTES;
            #pragma unroll
            for (int p = 0; p < 4; p++)
                LDSM_X4(bnxt[p], sn + boff + p * (16 * ROW_BYTES));
        }

        #pragma unroll
        for (int tm = 0; tm < 2; tm++)
            #pragma unroll
            for (int p = 0; p < 4; p++) {
                MMA16816(acc[tm][2 * p + 0], afr[tm], bcur[p][0], bcur[p][2]);
                MMA16816(acc[tm][2 * p + 1], afr[tm], bcur[p][1], bcur[p][3]);
            }
        #pragma unroll
        for (int p = 0; p < 4; p++)
            #pragma unroll
            for (int q = 0; q < 4; q++) bcur[p][q] = bnxt[p][q];
    }

    // ---------------- Epilogue ----------------
    const float gam = __ldg(gamma_p);
    #pragma unroll
    for (int tm = 0; tm < 2; tm++) {
        const int m0 = mbase + wm * 32 + tm * 16 + (lid >> 2);
        const float x2a = g_x2[m0];
        const float x2b = g_x2[m0 + 8];
        #pragma unroll
        for (int nn = 0; nn < 8; nn++) {
            const int n0 = nbase + wn * 64 + nn * 8 + (lid & 3) * 2;
            const float y2a = g_y2[n0];
            const float y2b = g_y2[n0 + 1];
            const float* c = acc[tm][nn];
            float2 v0, v1;
            v0.x = __expf(-gam * fmaxf(x2a + y2a - 2.0f * c[0], 0.0f));
            v0.y = __expf(-gam * fmaxf(x2a + y2b - 2.0f * c[1], 0.0f));
            v1.x = __expf(-gam * fmaxf(x2b + y2a - 2.0f * c[2], 0.0f));
            v1.y = __expf(-gam * fmaxf(x2b + y2b - 2.0f * c[3], 0.0f));
            *reinterpret_cast<float2*>(out + (size_t)m0 * NYR + n0) = v0;
            *reinterpret_cast<float2*>(out + (size_t)(m0 + 8) * NYR + n0) = v1;
        }
    }
}

extern "C" void kernel_launch(void* const* d_in, const int* in_sizes, int n_in,
                              void* d_out, int out_size) {
    const float* x = (const float*)d_in[0];
    const float* y = (const float*)d_in[1];
    const float* gamma = (const float*)d_in[2];
    float* out = (float*)d_out;

    rbf_prep_kernel<<<NXR + NYR, 128>>>(x, y);

    cudaFuncSetAttribute(rbf_gemm_kernel,
                         cudaFuncAttributeMaxDynamicSharedMemorySize, SMEM_TOTAL);
    dim3 grid(NYR / TN, NXR / TM);
    rbf_gemm_kernel<<<grid, 256, SMEM_TOTAL>>>(out, gamma);
}

// round 8
// speedup vs baseline: 1.0662x; 1.0086x over previous
#include <cuda_runtime.h>
#include <cuda_bf16.h>
#include <cstdint>

// Problem dims
#define NXR 8192
#define NYR 8192
#define DK  512

// Tile config: CTA 128x128, 8 warps each 32x64, K-step 64, 3 stages, 2 CTAs/SM
#define TM 128
#define TN 128
#define TK 64
#define KSTEPS (DK / TK)          // 8
#define STAGES 3

// SMEM: rows padded to 72 b16 (144B) for conflict-free ldmatrix.
#define ASTRIDE_B16 72
#define ROW_BYTES    (ASTRIDE_B16 * 2)               // 144
#define A_TILE_BYTES (TM * ROW_BYTES)                // 18432
#define B_TILE_BYTES (TN * ROW_BYTES)                // 18432
#define STAGE_BYTES  (A_TILE_BYTES + B_TILE_BYTES)   // 36864
#define SMEM_TOTAL   (STAGES * STAGE_BYTES)          // 110592

// bf16 scratch + row norms (device globals: no allocation allowed)
__device__ __nv_bfloat16 g_Xb[(size_t)NXR * DK];
__device__ __nv_bfloat16 g_Yb[(size_t)NYR * DK];
__device__ float g_x2[NXR];
__device__ float g_y2[NYR];

// ---------------- PTX helpers ----------------
__device__ __forceinline__ uint32_t smem_u32(const void* p) {
    uint32_t a;
    asm("{ .reg .u64 t; cvta.to.shared.u64 t, %1; cvt.u32.u64 %0, t; }" : "=r"(a) : "l"(p));
    return a;
}

#define CP_ASYNC16(saddr, gptr) \
    asm volatile("cp.async.cg.shared.global [%0], [%1], 16;" \
                 :: "r"(saddr), "l"(gptr) : "memory")

#define CP_COMMIT() asm volatile("cp.async.commit_group;" ::: "memory")
#define CP_WAIT(n)  asm volatile("cp.async.wait_group %0;" :: "n"(n) : "memory")

#define LDSM_X4(r, addr) \
    asm volatile("ldmatrix.sync.aligned.m8n8.x4.shared.b16 {%0,%1,%2,%3}, [%4];" \
                 : "=r"((r)[0]), "=r"((r)[1]), "=r"((r)[2]), "=r"((r)[3]) : "r"(addr))

#define MMA16816(d, a, b0, b1) \
    asm volatile("mma.sync.aligned.m16n8k16.row.col.f32.bf16.bf16.f32 " \
                 "{%0,%1,%2,%3}, {%4,%5,%6,%7}, {%8,%9}, {%0,%1,%2,%3};" \
                 : "+f"((d)[0]), "+f"((d)[1]), "+f"((d)[2]), "+f"((d)[3]) \
                 : "r"((a)[0]), "r"((a)[1]), "r"((a)[2]), "r"((a)[3]), \
                   "r"(b0), "r"(b1))

// ---------------- Prepass: f32 -> bf16 + row squared norms ----------------
__global__ void __launch_bounds__(128) rbf_prep_kernel(
    const float* __restrict__ x, const float* __restrict__ y) {
    __shared__ float red[4];
    int b = blockIdx.x;
    int t = threadIdx.x;
    const float* src;
    __nv_bfloat16* dst;
    float* nrm;
    int row;
    if (b < NXR) { row = b;       src = x + (size_t)row * DK; dst = g_Xb + (size_t)row * DK; nrm = g_x2; }
    else         { row = b - NXR; src = y + (size_t)row * DK; dst = g_Yb + (size_t)row * DK; nrm = g_y2; }

    float4 v = reinterpret_cast<const float4*>(src)[t];          // 128 threads x 4 = 512
    float s = v.x * v.x + v.y * v.y + v.z * v.z + v.w * v.w;
    __nv_bfloat162 h0 = __floats2bfloat162_rn(v.x, v.y);
    __nv_bfloat162 h1 = __floats2bfloat162_rn(v.z, v.w);
    reinterpret_cast<__nv_bfloat162*>(dst)[t * 2 + 0] = h0;
    reinterpret_cast<__nv_bfloat162*>(dst)[t * 2 + 1] = h1;

    #pragma unroll
    for (int o = 16; o; o >>= 1) s += __shfl_xor_sync(0xffffffffu, s, o);
    if ((t & 31) == 0) red[t >> 5] = s;
    __syncthreads();
    if (t == 0) nrm[row] = red[0] + red[1] + red[2] + red[3];
}

// ---------------- Main kernel: pipelined mma.sync GEMM + RBF epilogue ----------------
__global__ void __launch_bounds__(256, 2) rbf_gemm_kernel(
    float* __restrict__ out, const float* __restrict__ gamma_p) {
    extern __shared__ char smem[];
    const uint32_t sb = smem_u32(smem);
    const int tid = threadIdx.x;
    const int wid = tid >> 5;
    const int lid = tid & 31;
    const int wm = wid & 3;            // warp row: 32-row slab (4)
    const int wn = wid >> 2;           // warp col: 64-col slab (2)
    const int mbase = blockIdx.y * TM;
    const int nbase = blockIdx.x * TN;

    // ---- cp.async assignment: A/B each 128 rows x 8 segs(16B) = 1024 chunks,
    //      4 per thread. idx = tid + h*256, row = idx>>3, seg = idx&7.
    const int lr0 = tid >> 3,           ls0 = tid & 7;
    const int lr1 = (tid + 256) >> 3,   ls1 = (tid + 256) & 7;
    const int lr2 = (tid + 512) >> 3,   ls2 = (tid + 512) & 7;
    const int lr3 = (tid + 768) >> 3,   ls3 = (tid + 768) & 7;
    // Bumped by TK elements per loaded k-step.
    const __nv_bfloat16* ap0 = g_Xb + (size_t)(mbase + lr0) * DK + ls0 * 8;
    const __nv_bfloat16* ap1 = g_Xb + (size_t)(mbase + lr1) * DK + ls1 * 8;
    const __nv_bfloat16* ap2 = g_Xb + (size_t)(mbase + lr2) * DK + ls2 * 8;
    const __nv_bfloat16* ap3 = g_Xb + (size_t)(mbase + lr3) * DK + ls3 * 8;
    const __nv_bfloat16* bp0 = g_Yb + (size_t)(nbase + lr0) * DK + ls0 * 8;
    const __nv_bfloat16* bp1 = g_Yb + (size_t)(nbase + lr1) * DK + ls1 * 8;
    const __nv_bfloat16* bp2 = g_Yb + (size_t)(nbase + lr2) * DK + ls2 * 8;
    const __nv_bfloat16* bp3 = g_Yb + (size_t)(nbase + lr3) * DK + ls3 * 8;
    const uint32_t so0 = (uint32_t)(lr0 * ROW_BYTES + ls0 * 16);
    const uint32_t so1 = (uint32_t)(lr1 * ROW_BYTES + ls1 * 16);
    const uint32_t so2 = (uint32_t)(lr2 * ROW_BYTES + ls2 * 16);
    const uint32_t so3 = (uint32_t)(lr3 * ROW_BYTES + ls3 * 16);

    int ldk = 0;
    #pragma unroll
    for (int s = 0; s < STAGES - 1; s++) {
        const uint32_t st = sb + s * STAGE_BYTES;
        CP_ASYNC16(st + so0, ap0);  CP_ASYNC16(st + so1, ap1);
        CP_ASYNC16(st + so2, ap2);  CP_ASYNC16(st + so3, ap3);
        CP_ASYNC16(st + A_TILE_BYTES + so0, bp0);
        CP_ASYNC16(st + A_TILE_BYTES + so1, bp1);
        CP_ASYNC16(st + A_TILE_BYTES + so2, bp2);
        CP_ASYNC16(st + A_TILE_BYTES + so3, bp3);
        CP_COMMIT();
        ap0 += TK; ap1 += TK; ap2 += TK; ap3 += TK;
        bp0 += TK; bp1 += TK; bp2 += TK; bp3 += TK;
        ldk++;
    }

    // acc[tm 0..1][nn 0..7][4] : warp 32x64 tile
    float acc[2][8][4];
    #pragma unroll
    for (int i = 0; i < 2; i++)
        #pragma unroll
        for (int j = 0; j < 8; j++)
            #pragma unroll
            for (int q = 0; q < 4; q++) acc[i][j][q] = 0.0f;

    const int lrow = lid & 15;
    const int lhalf = lid >> 4;
    const uint32_t aoff = (uint32_t)((wm * 32 + lrow) * ROW_BYTES + lhalf * 16);
    const uint32_t boff = (uint32_t)(A_TILE_BYTES + (wn * 64 + lrow) * ROW_BYTES + lhalf * 16);

    CP_WAIT(STAGES - 2);
    __syncthreads();

    for (int k = 0; k < KSTEPS; k++) {
        const uint32_t st = sb + (k % STAGES) * STAGE_BYTES;

        // Issue next-stage loads first; they drain under the MMA burst.
        if (ldk < KSTEPS) {
            const uint32_t ls = sb + (ldk % STAGES) * STAGE_BYTES;
            CP_ASYNC16(ls + so0, ap0);  CP_ASYNC16(ls + so1, ap1);
            CP_ASYNC16(ls + so2, ap2);  CP_ASYNC16(ls + so3, ap3);
            CP_ASYNC16(ls + A_TILE_BYTES + so0, bp0);
            CP_ASYNC16(ls + A_TILE_BYTES + so1, bp1);
            CP_ASYNC16(ls + A_TILE_BYTES + so2, bp2);
            CP_ASYNC16(ls + A_TILE_BYTES + so3, bp3);
            ap0 += TK; ap1 += TK; ap2 += TK; ap3 += TK;
            bp0 += TK; bp1 += TK; bp2 += TK; bp3 += TK;
            ldk++;
        }
        CP_COMMIT();

        // 4 x k16 sub-steps, fragments loaded just-in-time, no register copies
        #pragma unroll
        for (int kk = 0; kk < 4; kk++) {
            uint32_t a[2][4], b[4][4];
            #pragma unroll
            for (int p = 0; p < 4; p++)
                LDSM_X4(b[p], st + boff + kk * 32 + p * (16 * ROW_BYTES));
            #pragma unroll
            for (int tm = 0; tm < 2; tm++)
                LDSM_X4(a[tm], st + aoff + kk * 32 + tm * (16 * ROW_BYTES));

            #pragma unroll
            for (int tm = 0; tm < 2; tm++)
                #pragma unroll
                for (int p = 0; p < 4; p++) {
                    MMA16816(acc[tm][2 * p + 0], a[tm], b[p][0], b[p][2]);
                    MMA16816(acc[tm][2 * p + 1], a[tm], b[p][1], b[p][3]);
                }
        }

        CP_WAIT(STAGES - 2);
        __syncthreads();
    }

    // ---------------- Epilogue ----------------
    const float gam = __ldg(gamma_p);
    #pragma unroll
    for (int tm = 0; tm < 2; tm++) {
        const int m0 = mbase + wm * 32 + tm * 16 + (lid >> 2);
        const float x2a = g_x2[m0];
        const float x2b = g_x2[m0 + 8];
        #pragma unroll
        for (int nn = 0; nn < 8; nn++) {
            const int n0 = nbase + wn * 64 + nn * 8 + (lid & 3) * 2;
            const float y2a = g_y2[n0];
            const float y2b = g_y2[n0 + 1];
            const float* c = acc[tm][nn];
            float2 v0, v1;
            v0.x = __expf(-gam * fmaxf(x2a + y2a - 2.0f * c[0], 0.0f));
            v0.y = __expf(-gam * fmaxf(x2a + y2b - 2.0f * c[1], 0.0f));
            v1.x = __expf(-gam * fmaxf(x2b + y2a - 2.0f * c[2], 0.0f));
            v1.y = __expf(-gam * fmaxf(x2b + y2b - 2.0f * c[3], 0.0f));
            *reinterpret_cast<float2*>(out + (size_t)m0 * NYR + n0) = v0;
            *reinterpret_cast<float2*>(out + (size_t)(m0 + 8) * NYR + n0) = v1;
        }
    }
}

extern "C" void kernel_launch(void* const* d_in, const int* in_sizes, int n_in,
                              void* d_out, int out_size) {
    const float* x = (const float*)d_in[0];
    const float* y = (const float*)d_in[1];
    const float* gamma = (const float*)d_in[2];
    float* out = (float*)d_out;

    rbf_prep_kernel<<<NXR + NYR, 128>>>(x, y);

    cudaFuncSetAttribute(rbf_gemm_kernel,
                         cudaFuncAttributeMaxDynamicSharedMemorySize, SMEM_TOTAL);
    dim3 grid(NYR / TN, NXR / TM);
    rbf_gemm_kernel<<<grid, 256, SMEM_TOTAL>>>(out, gamma);
}

// round 9
// speedup vs baseline: 1.1310x; 1.0608x over previous
#include <cuda_runtime.h>
#include <cuda_bf16.h>
#include <cstdint>

// Problem dims
#define NXR 8192
#define NYR 8192
#define DK  512

// Tile config: CTA 128x128, 8 warps each 32x64, K-step 64, 3 stages, 2 CTAs/SM
#define TM 128
#define TN 128
#define TK 64
#define KSTEPS (DK / TK)          // 8
#define STAGES 3

// SMEM: rows padded to 72 b16 (144B) for conflict-free ldmatrix.
#define ASTRIDE_B16 72
#define ROW_BYTES    (ASTRIDE_B16 * 2)               // 144
#define A_TILE_BYTES (TM * ROW_BYTES)                // 18432
#define B_TILE_BYTES (TN * ROW_BYTES)                // 18432
#define STAGE_BYTES  (A_TILE_BYTES + B_TILE_BYTES)   // 36864
#define SMEM_TOTAL   (STAGES * STAGE_BYTES)          // 110592

// bf16 scratch + row norms (device globals: no allocation allowed)
__device__ __nv_bfloat16 g_Xb[(size_t)NXR * DK];
__device__ __nv_bfloat16 g_Yb[(size_t)NYR * DK];
__device__ float g_x2[NXR];
__device__ float g_y2[NYR];

// ---------------- PTX helpers ----------------
__device__ __forceinline__ uint32_t smem_u32(const void* p) {
    uint32_t a;
    asm("{ .reg .u64 t; cvta.to.shared.u64 t, %1; cvt.u32.u64 %0, t; }" : "=r"(a) : "l"(p));
    return a;
}

#define CP_ASYNC16(saddr, gptr) \
    asm volatile("cp.async.cg.shared.global [%0], [%1], 16;" \
                 :: "r"(saddr), "l"(gptr) : "memory")

#define CP_COMMIT() asm volatile("cp.async.commit_group;" ::: "memory")
#define CP_WAIT(n)  asm volatile("cp.async.wait_group %0;" :: "n"(n) : "memory")

#define LDSM_X4(r, addr) \
    asm volatile("ldmatrix.sync.aligned.m8n8.x4.shared.b16 {%0,%1,%2,%3}, [%4];" \
                 : "=r"((r)[0]), "=r"((r)[1]), "=r"((r)[2]), "=r"((r)[3]) : "r"(addr))

#define MMA16816(d, a, b0, b1) \
    asm volatile("mma.sync.aligned.m16n8k16.row.col.f32.bf16.bf16.f32 " \
                 "{%0,%1,%2,%3}, {%4,%5,%6,%7}, {%8,%9}, {%0,%1,%2,%3};" \
                 : "+f"((d)[0]), "+f"((d)[1]), "+f"((d)[2]), "+f"((d)[3]) \
                 : "r"((a)[0]), "r"((a)[1]), "r"((a)[2]), "r"((a)[3]), \
                   "r"(b0), "r"(b1))

// Issue the 8 cp.asyncs for one stage. Only 2 live pointers; the rest are
// compile-time immediate offsets (rows +32/+64/+96 -> +32*DK elems, smem
// rows -> +32*ROW_BYTES).
#define LOAD_STAGE(ls, apb, bpb, so0) do {                                    \
    CP_ASYNC16((ls) + (so0),                       (apb));                    \
    CP_ASYNC16((ls) + (so0) + 32 * ROW_BYTES,      (apb) + 32 * DK);          \
    CP_ASYNC16((ls) + (so0) + 64 * ROW_BYTES,      (apb) + 64 * DK);          \
    CP_ASYNC16((ls) + (so0) + 96 * ROW_BYTES,      (apb) + 96 * DK);          \
    CP_ASYNC16((ls) + A_TILE_BYTES + (so0),                  (bpb));          \
    CP_ASYNC16((ls) + A_TILE_BYTES + (so0) + 32 * ROW_BYTES, (bpb) + 32 * DK);\
    CP_ASYNC16((ls) + A_TILE_BYTES + (so0) + 64 * ROW_BYTES, (bpb) + 64 * DK);\
    CP_ASYNC16((ls) + A_TILE_BYTES + (so0) + 96 * ROW_BYTES, (bpb) + 96 * DK);\
} while (0)

#define MMA_BURST(bb) do {                                                    \
    _Pragma("unroll")                                                         \
    for (int tm = 0; tm < 2; tm++)                                            \
        _Pragma("unroll")                                                     \
        for (int p = 0; p < 4; p++) {                                         \
            MMA16816(acc[tm][2 * p + 0], afr[tm], (bb)[p][0], (bb)[p][2]);    \
            MMA16816(acc[tm][2 * p + 1], afr[tm], (bb)[p][1], (bb)[p][3]);    \
        }                                                                     \
} while (0)

// ---------------- Prepass: f32 -> bf16 + row squared norms ----------------
__global__ void __launch_bounds__(128) rbf_prep_kernel(
    const float* __restrict__ x, const float* __restrict__ y) {
    __shared__ float red[4];
    int b = blockIdx.x;
    int t = threadIdx.x;
    const float* src;
    __nv_bfloat16* dst;
    float* nrm;
    int row;
    if (b < NXR) { row = b;       src = x + (size_t)row * DK; dst = g_Xb + (size_t)row * DK; nrm = g_x2; }
    else         { row = b - NXR; src = y + (size_t)row * DK; dst = g_Yb + (size_t)row * DK; nrm = g_y2; }

    float4 v = reinterpret_cast<const float4*>(src)[t];
    float s = v.x * v.x + v.y * v.y + v.z * v.z + v.w * v.w;
    __nv_bfloat162 h0 = __floats2bfloat162_rn(v.x, v.y);
    __nv_bfloat162 h1 = __floats2bfloat162_rn(v.z, v.w);
    reinterpret_cast<__nv_bfloat162*>(dst)[t * 2 + 0] = h0;
    reinterpret_cast<__nv_bfloat162*>(dst)[t * 2 + 1] = h1;

    #pragma unroll
    for (int o = 16; o; o >>= 1) s += __shfl_xor_sync(0xffffffffu, s, o);
    if ((t & 31) == 0) red[t >> 5] = s;
    __syncthreads();
    if (t == 0) nrm[row] = red[0] + red[1] + red[2] + red[3];
}

// ---------------- Main kernel: cross-sync pipelined GEMM + RBF epilogue ----------------
__global__ void __launch_bounds__(256, 2) rbf_gemm_kernel(
    float* __restrict__ out, const float* __restrict__ gamma_p) {
    extern __shared__ char smem[];
    const uint32_t sb = smem_u32(smem);
    const int tid = threadIdx.x;
    const int wid = tid >> 5;
    const int lid = tid & 31;
    const int wm = wid & 3;            // warp row: 32-row slab (4)
    const int wn = wid >> 2;           // warp col: 64-col slab (2)
    const int mbase = blockIdx.y * TM;
    const int nbase = blockIdx.x * TN;

    // cp.async base assignment: row lr0 = tid>>3 (0..31), seg ls0 = tid&7.
    const int lr0 = tid >> 3, ls0 = tid & 7;
    const __nv_bfloat16* apb = g_Xb + (size_t)(mbase + lr0) * DK + ls0 * 8;
    const __nv_bfloat16* bpb = g_Yb + (size_t)(nbase + lr0) * DK + ls0 * 8;
    const uint32_t so0 = (uint32_t)(lr0 * ROW_BYTES + ls0 * 16);

    int ldk = 0;
    #pragma unroll
    for (int s = 0; s < STAGES - 1; s++) {
        LOAD_STAGE(sb + s * STAGE_BYTES, apb, bpb, so0);
        CP_COMMIT();
        apb += TK; bpb += TK;
        ldk++;
    }

    float acc[2][8][4];
    #pragma unroll
    for (int i = 0; i < 2; i++)
        #pragma unroll
        for (int j = 0; j < 8; j++)
            #pragma unroll
            for (int q = 0; q < 4; q++) acc[i][j][q] = 0.0f;

    const int lrow = lid & 15;
    const int lhalf = lid >> 4;
    const uint32_t aoff = (uint32_t)((wm * 32 + lrow) * ROW_BYTES + lhalf * 16);
    const uint32_t boff = (uint32_t)(A_TILE_BYTES + (wn * 64 + lrow) * ROW_BYTES + lhalf * 16);

    // Prologue: stage 0 landed; prime b0 = B(stage0, kk=0).
    CP_WAIT(STAGES - 2);
    __syncthreads();
    uint32_t b0[4][4], b1[4][4], afr[2][4];
    #pragma unroll
    for (int p = 0; p < 4; p++)
        LDSM_X4(b0[p], sb + boff + p * (16 * ROW_BYTES));

    for (int k = 0; k < KSTEPS; k++) {
        const uint32_t st = sb + (k % STAGES) * STAGE_BYTES;

        // kk=0: load B(kk=1)->b1, A(kk=0); MMA on b0
        #pragma unroll
        for (int p = 0; p < 4; p++)
            LDSM_X4(b1[p], st + boff + 1 * 32 + p * (16 * ROW_BYTES));
        #pragma unroll
        for (int tm = 0; tm < 2; tm++)
            LDSM_X4(afr[tm], st + aoff + 0 * 32 + tm * (16 * ROW_BYTES));
        MMA_BURST(b0);

        // Issue next-stage cp.asyncs (drain under MMA bursts).
        if (ldk < KSTEPS) {
            LOAD_STAGE(sb + (ldk % STAGES) * STAGE_BYTES, apb, bpb, so0);
            apb += TK; bpb += TK;
            ldk++;
        }
        CP_COMMIT();

        // kk=1: load B(kk=2)->b0, A(kk=1); MMA on b1
        #pragma unroll
        for (int p = 0; p < 4; p++)
            LDSM_X4(b0[p], st + boff + 2 * 32 + p * (16 * ROW_BYTES));
        #pragma unroll
        for (int tm = 0; tm < 2; tm++)
            LDSM_X4(afr[tm], st + aoff + 1 * 32 + tm * (16 * ROW_BYTES));
        MMA_BURST(b1);

        // kk=2: load B(kk=3)->b1, A(kk=2); MMA on b0
        #pragma unroll
        for (int p = 0; p < 4; p++)
            LDSM_X4(b1[p], st + boff + 3 * 32 + p * (16 * ROW_BYTES));
        #pragma unroll
        for (int tm = 0; tm < 2; tm++)
            LDSM_X4(afr[tm], st + aoff + 2 * 32 + tm * (16 * ROW_BYTES));
        MMA_BURST(b0);

        // kk=3: A read pre-sync; then wait+sync; then prime b0 from stage k+1
        // (its ldsm storm hides under kk=3's MMA burst below).
        #pragma unroll
        for (int tm = 0; tm < 2; tm++)
            LDSM_X4(afr[tm], st + aoff + 3 * 32 + tm * (16 * ROW_BYTES));
        CP_WAIT(STAGES - 2);
        __syncthreads();
        if (k + 1 < KSTEPS) {
            const uint32_t sn = sb + ((k + 1) % STAGES) * STAGE_BYTES;
            #pragma unroll
            for (int p = 0; p < 4; p++)
                LDSM_X4(b0[p], sn + boff + p * (16 * ROW_BYTES));
        }
        MMA_BURST(b1);
    }

    // ---------------- Epilogue ----------------
    const float gam = __ldg(gamma_p);
    #pragma unroll
    for (int tm = 0; tm < 2; tm++) {
        const int m0 = mbase + wm * 32 + tm * 16 + (lid >> 2);
        const float x2a = g_x2[m0];
        const float x2b = g_x2[m0 + 8];
        #pragma unroll
        for (int nn = 0; nn < 8; nn++) {
            const int n0 = nbase + wn * 64 + nn * 8 + (lid & 3) * 2;
            const float y2a = g_y2[n0];
            const float y2b = g_y2[n0 + 1];
            const float* c = acc[tm][nn];
            float2 v0, v1;
            v0.x = __expf(-gam * fmaxf(x2a + y2a - 2.0f * c[0], 0.0f));
            v0.y = __expf(-gam * fmaxf(x2a + y2b - 2.0f * c[1], 0.0f));
            v1.x = __expf(-gam * fmaxf(x2b + y2a - 2.0f * c[2], 0.0f));
            v1.y = __expf(-gam * fmaxf(x2b + y2b - 2.0f * c[3], 0.0f));
            *reinterpret_cast<float2*>(out + (size_t)m0 * NYR + n0) = v0;
            *reinterpret_cast<float2*>(out + (size_t)(m0 + 8) * NYR + n0) = v1;
        }
    }
}

extern "C" void kernel_launch(void* const* d_in, const int* in_sizes, int n_in,
                              void* d_out, int out_size) {
    const float* x = (const float*)d_in[0];
    const float* y = (const float*)d_in[1];
    const float* gamma = (const float*)d_in[2];
    float* out = (float*)d_out;

    rbf_prep_kernel<<<NXR + NYR, 128>>>(x, y);

    cudaFuncSetAttribute(rbf_gemm_kernel,
                         cudaFuncAttributeMaxDynamicSharedMemorySize, SMEM_TOTAL);
    dim3 grid(NYR / TN, NXR / TM);
    rbf_gemm_kernel<<<grid, 256, SMEM_TOTAL>>>(out, gamma);
}